// round 10
// baseline (speedup 1.0000x reference)
#include <cuda_runtime.h>
#include <math.h>
#include <stdint.h>

#define B_ 8
#define N_ 4096
#define K_ 16
#define D_ 256
#define M_ (B_*N_)          // 32768 query rows

__device__ int   g_idx[M_*K_];        // 2 MB
__device__ float g_agg[M_*D_];        // 33.5 MB

// tf32 fragment-major weights (filled by prep_kernel each launch)
__device__ float g_W2f [8*8*32*4];    // [kt8][ntp8][lane32][4]
__device__ float g_W3f [16*16*32*4];  // [kt16][ntp16][lane32][4]
__device__ float g_Wa1f[32*16*32*4];  // [kt32][ntp16][lane32][4]
__device__ float g_Wa2f[32*16*32*4];

// ---------------------------------------------------------------------------
__device__ __forceinline__ float tf32r(float x) {
    uint32_t u;
    asm("cvt.rna.tf32.f32 %0, %1;" : "=r"(u) : "f"(x));
    return __uint_as_float(u);
}
// D += A(m16k8,row) * B(k8n8,col); fp32 accum, tf32 inputs
__device__ __forceinline__ void mma_tf32(float* c, uint4 a, uint32_t b0, uint32_t b1) {
    asm volatile(
        "mma.sync.aligned.m16n8k8.row.col.f32.tf32.tf32.f32 "
        "{%0,%1,%2,%3}, {%4,%5,%6,%7}, {%8,%9}, {%0,%1,%2,%3};"
        : "+f"(c[0]), "+f"(c[1]), "+f"(c[2]), "+f"(c[3])
        : "r"(a.x), "r"(a.y), "r"(a.z), "r"(a.w), "r"(b0), "r"(b1));
}

// ---------------------------------------------------------------------------
// Kernel 0: convert weights to tf32 fragment-major layouts.
// ---------------------------------------------------------------------------
__global__ void prep_kernel(const float* __restrict__ W2, const float* __restrict__ W3,
                            const float* __restrict__ Wa1, const float* __restrict__ Wa2)
{
    int idx = blockIdx.x * 256 + threadIdx.x;   // 43008 total float4 entries
    if (idx >= 43008) return;
    const float* W; float* dst; int NT, NTP, r;
    if (idx < 2048)       { r = idx;         W = W2;  dst = g_W2f;  NT = 128; NTP = 8;  }
    else if (idx < 10240) { r = idx - 2048;  W = W3;  dst = g_W3f;  NT = 256; NTP = 16; }
    else if (idx < 26624) { r = idx - 10240; W = Wa1; dst = g_Wa1f; NT = 256; NTP = 16; }
    else                  { r = idx - 26624; W = Wa2; dst = g_Wa2f; NT = 256; NTP = 16; }
    int lane = r & 31, ntp = (r >> 5) % NTP, kt = (r >> 5) / NTP;
    int g = lane >> 2, tg = lane & 3;
    int nt0 = 2*ntp, nt1 = 2*ntp + 1;
    float4 v;
    v.x = tf32r(W[(kt*8 + tg    )*NT + nt0*8 + g]);
    v.y = tf32r(W[(kt*8 + tg + 4)*NT + nt0*8 + g]);
    v.z = tf32r(W[(kt*8 + tg    )*NT + nt1*8 + g]);
    v.w = tf32r(W[(kt*8 + tg + 4)*NT + nt1*8 + g]);
    ((float4*)dst)[(kt*NTP + ntp)*32 + lane] = v;
}

// ---------------------------------------------------------------------------
// Kernel 1: brute-force kNN — measured-optimal R2 configuration (FROZEN).
// ---------------------------------------------------------------------------
__global__ __launch_bounds__(256) void knn_kernel(const float* __restrict__ coords)
{
    __shared__ float4 tile[256];
    __shared__ float  sd[256 * K_];
    __shared__ int    si[256 * K_];

    const int t = threadIdx.x;
    const int b  = blockIdx.x >> 5;
    const int q0 = (blockIdx.x & 31) << 7;
    const int q  = q0 + (t & 127);
    const int half = t >> 7;
    const float* cb = coords + (size_t)b * N_ * 3;

    float qx = cb[q*3+0], qy = cb[q*3+1], qz = cb[q*3+2];
    float qsq = qx*qx + qy*qy + qz*qz;

    float best[K_]; int bidx[K_];
#pragma unroll
    for (int s = 0; s < K_; s++) { best[s] = 3.4e38f; bidx[s] = 0; }

    const int base = half * 2048;
    for (int c0 = 0; c0 < 2048; c0 += 128) {
        __syncthreads();
        {
            int m = (t < 128) ? (c0 + t) : (2048 + c0 + (t - 128));
            float x = cb[m*3+0], y = cb[m*3+1], z = cb[m*3+2];
            tile[t] = make_float4(x, y, z, x*x + y*y + z*z);
        }
        __syncthreads();
        const float4* tl = tile + half * 128;
#pragma unroll 4
        for (int mm = 0; mm < 128; mm++) {
            float4 c = tl[mm];
            float d2 = qsq + c.w - 2.0f*(qx*c.x + qy*c.y + qz*c.z);
            if (d2 < best[K_-1]) {
                float d = d2; int id = base + c0 + mm;
#pragma unroll
                for (int s = 0; s < K_; s++) {
                    if (d < best[s]) {
                        float td = best[s]; int ti = bidx[s];
                        best[s] = d; bidx[s] = id;
                        d = td; id = ti;
                    }
                }
            }
        }
    }

#pragma unroll
    for (int s = 0; s < K_; s++) { sd[t*K_ + s] = best[s]; si[t*K_ + s] = bidx[s]; }
    __syncthreads();

    if (t < 128) {
        const float* da = sd + t*K_;        const int* xa = si + t*K_;
        const float* db = sd + (t+128)*K_;  const int* xb = si + (t+128)*K_;
        int ia = 0, ib = 0;
        int* o = g_idx + (size_t)(b*N_ + q0 + t) * K_;
#pragma unroll
        for (int s = 0; s < K_; s++) {
            float va = (ia < K_) ? da[ia] : 3.4e38f;
            float vb = (ib < K_) ? db[ib] : 3.4e38f;
            bool takeA = (va < vb) || (va == vb && ((ia < K_ ? xa[ia] : 0x7fffffff) <
                                                    (ib < K_ ? xb[ib] : 0x7fffffff)));
            if (takeA) { o[s] = xa[ia]; ia++; }
            else       { o[s] = xb[ib]; ib++; }
        }
    }
}

// ---------------------------------------------------------------------------
// Warp-per-row LayerNorm with runtime row stride. NW warps per block.
// ---------------------------------------------------------------------------
template<int W, bool RELU, int NW>
__device__ __forceinline__ void ln_rows_s(float* buf, int stride, int rows,
                                          const float* __restrict__ g,
                                          const float* __restrict__ be)
{
    const int wid = threadIdx.x >> 5, lane = threadIdx.x & 31;
    constexpr int C = W / 32;
    for (int r = wid; r < rows; r += NW) {
        float* h = buf + r * stride;
        float v[C]; float s = 0.f;
#pragma unroll
        for (int i = 0; i < C; i++) { v[i] = h[lane + i*32]; s += v[i]; }
#pragma unroll
        for (int o = 16; o; o >>= 1) s += __shfl_xor_sync(0xffffffffu, s, o);
        float mean = s * (1.0f / W);
        float s2 = 0.f;
#pragma unroll
        for (int i = 0; i < C; i++) { float d = v[i] - mean; s2 += d*d; }
#pragma unroll
        for (int o = 16; o; o >>= 1) s2 += __shfl_xor_sync(0xffffffffu, s2, o);
        float rstd = rsqrtf(s2 * (1.0f / W) + 1e-5f);
#pragma unroll
        for (int i = 0; i < C; i++) {
            int c = lane + i*32;
            float o2 = (v[i] - mean) * rstd * g[c] + be[c];
            if (RELU) o2 = fmaxf(o2, 0.f);
            h[c] = o2;
        }
    }
}

// cvt fp32 smem matrix (16*MT rows x KT*8 cols, stride) -> A-fragment tf32.
template<int KT, int MT>
__device__ __forceinline__ void cvt_to_afrag(const float* src, int sstride,
                                             float* dstATF, int tid, int nthr)
{
    const int total = KT * MT * 32 * 4;
    for (int idx = tid; idx < total; idx += nthr) {
        int j    = idx & 3;
        int lane = (idx >> 2) & 31;
        int mt   = (idx >> 7) % MT;
        int kt   = (idx >> 7) / MT;
        int row  = mt*16 + (lane >> 2) + (j & 1)*8;
        int col  = kt*8 + (lane & 3) + ((j >> 1) & 1)*4;
        dstATF[idx] = tf32r(src[row*sstride + col]);
    }
}

// ---------------------------------------------------------------------------
// Kernel 2: fused geom features + encoder MLP (10->64->128->256) + mean over K
// One block = 8 queries = 128 rows, 512 threads (16 warps).
// Geom 4-way thread-parallel; stage 3 fused m32xn64 warp tile (acc[2][8][4]).
// smem floats: bufF[33280] | sATF[16384] = 198656 B
// ---------------------------------------------------------------------------
#define ENC_G 8
#define ENC_R 128
#define ENC_SMEM_FLOATS (33280 + 16384)

__global__ __launch_bounds__(512, 1) void encoder_kernel(
    const float* __restrict__ coords,
    const float* __restrict__ W1, const float* __restrict__ b1,
    const float* __restrict__ g1, const float* __restrict__ be1,
    const float* __restrict__ b2,
    const float* __restrict__ g2, const float* __restrict__ be2,
    const float* __restrict__ b3,
    const float* __restrict__ g3, const float* __restrict__ be3)
{
    extern __shared__ float sm[];
    float* bufF = sm;                  // 33280 (stride 64 / 136 / 260 over time)
    float* sATF = sm + 33280;          // 16384 (geom first, then A-fragments)
    const int t = threadIdx.x;
    const int w = t >> 5;
    const int lane = t & 31;
    const int g = lane >> 2, tg = lane & 3;
    const int q0 = blockIdx.x * ENC_G;

    {   // geometric features, 4 threads per row (phases: 0 = dist/rel/rn, 1-3 = one atan2)
        int row = t >> 2;
        int ph  = t & 3;
        int q  = q0 + (row >> 4);
        int kk = row & 15;
        int b  = q >> 12;
        int n  = q & (N_ - 1);
        const float* cb = coords + (size_t)b * N_ * 3;
        float qx = cb[n*3+0], qy = cb[n*3+1], qz = cb[n*3+2];
        int nb = g_idx[(size_t)q * K_ + kk];
        float rx = cb[nb*3+0] - qx, ry = cb[nb*3+1] - qy, rz = cb[nb*3+2] - qz;
        float dist = sqrtf(rx*rx + ry*ry + rz*rz);
        float inv  = 1.0f / (dist + 1e-6f);
        float nx = rx*inv, ny = ry*inv, nz = rz*inv;
        float* gm = sATF + row * 10;
        if (ph == 0) {
            gm[0] = dist; gm[1] = rx; gm[2] = ry; gm[3] = rz;
            gm[7] = nx; gm[8] = ny; gm[9] = nz;
        } else if (ph == 1) {
            gm[4] = atan2f(ny, nx);
        } else if (ph == 2) {
            gm[5] = atan2f(nz, nx);
        } else {
            gm[6] = atan2f(nz, ny);
        }
    }
    __syncthreads();

    // ---- stage 1 (fp32): geom[128][10] @ W1[10][64] -> bufF stride 64 ----
    {
        int j = t & 63, r0 = (t >> 6) * 16;
        float acc[16];
        float bj = b1[j];
#pragma unroll
        for (int r = 0; r < 16; r++) acc[r] = bj;
#pragma unroll
        for (int k = 0; k < 10; k++) {
            float wv = W1[k*64 + j];
#pragma unroll
            for (int r = 0; r < 16; r++)
                acc[r] = fmaf(wv, sATF[(r0 + r)*10 + k], acc[r]);
        }
#pragma unroll
        for (int r = 0; r < 16; r++) bufF[(r0 + r)*64 + j] = acc[r];
    }
    __syncthreads();
    ln_rows_s<64, true, 16>(bufF, 64, ENC_R, g1, be1);
    __syncthreads();

    // cvt h1 -> A-fragments (K=64 -> KT=8, MT=8)
    cvt_to_afrag<8, 8>(bufF, 64, sATF, t, 512);
    __syncthreads();

    // ---- stage 2 (mma): h1[128x64] @ W2[64x128] -> bufF stride 136 ----
    {
        const int mtg = w & 3;           // mtiles {2mtg, 2mtg+1}
        const int npg = w >> 2;          // ntps {2npg, 2npg+1} -> ntiles 4
        float acc[2][4][4];
#pragma unroll
        for (int a = 0; a < 2; a++)
#pragma unroll
            for (int c = 0; c < 4; c++)
#pragma unroll
                for (int k = 0; k < 4; k++) acc[a][c][k] = 0.f;
        const uint4* AT = (const uint4*)sATF;
        const uint4* BT = (const uint4*)g_W2f;
#pragma unroll
        for (int kt = 0; kt < 8; kt++) {
            uint4 a0 = AT[(kt*8 + 2*mtg    )*32 + lane];
            uint4 a1 = AT[(kt*8 + 2*mtg + 1)*32 + lane];
            uint4 bq0 = BT[(kt*8 + 2*npg    )*32 + lane];
            uint4 bq1 = BT[(kt*8 + 2*npg + 1)*32 + lane];
            mma_tf32(acc[0][0], a0, bq0.x, bq0.y);
            mma_tf32(acc[0][1], a0, bq0.z, bq0.w);
            mma_tf32(acc[0][2], a0, bq1.x, bq1.y);
            mma_tf32(acc[0][3], a0, bq1.z, bq1.w);
            mma_tf32(acc[1][0], a1, bq0.x, bq0.y);
            mma_tf32(acc[1][1], a1, bq0.z, bq0.w);
            mma_tf32(acc[1][2], a1, bq1.x, bq1.y);
            mma_tf32(acc[1][3], a1, bq1.z, bq1.w);
        }
#pragma unroll
        for (int a = 0; a < 2; a++) {
            int row = (2*mtg + a)*16 + g;
#pragma unroll
            for (int c = 0; c < 4; c++) {
                int col = (4*npg + c)*8 + 2*tg;
                float2 bb = *(const float2*)&b2[col];
                *(float2*)&bufF[ row     *136 + col] =
                    make_float2(acc[a][c][0] + bb.x, acc[a][c][1] + bb.y);
                *(float2*)&bufF[(row + 8)*136 + col] =
                    make_float2(acc[a][c][2] + bb.x, acc[a][c][3] + bb.y);
            }
        }
    }
    __syncthreads();
    ln_rows_s<128, true, 16>(bufF, 136, ENC_R, g2, be2);
    __syncthreads();

    // cvt h2 -> A-fragments (K=128 -> KT=16, MT=8)
    cvt_to_afrag<16, 8>(bufF, 136, sATF, t, 512);
    __syncthreads();

    // ---- stage 3 (mma): h2[128x128] @ W3[128x256] -> bufF stride 260 ----
    // fused: warp = mtiles {2mtg,2mtg+1} x ntiles [8nq, 8nq+8), one A read per kt
    {
        const int mtg = w & 3;
        const int nq  = w >> 2;
        const uint4* AT = (const uint4*)sATF;
        const uint4* BT = (const uint4*)g_W3f;
        float acc[2][8][4];
#pragma unroll
        for (int a = 0; a < 2; a++)
#pragma unroll
            for (int c = 0; c < 8; c++)
#pragma unroll
                for (int k = 0; k < 4; k++) acc[a][c][k] = 0.f;
#pragma unroll
        for (int kt = 0; kt < 16; kt++) {
            uint4 a0 = AT[(kt*8 + 2*mtg    )*32 + lane];
            uint4 a1 = AT[(kt*8 + 2*mtg + 1)*32 + lane];
#pragma unroll
            for (int j = 0; j < 4; j++) {
                uint4 bq = BT[(kt*16 + 4*nq + j)*32 + lane];
                mma_tf32(acc[0][2*j    ], a0, bq.x, bq.y);
                mma_tf32(acc[0][2*j + 1], a0, bq.z, bq.w);
                mma_tf32(acc[1][2*j    ], a1, bq.x, bq.y);
                mma_tf32(acc[1][2*j + 1], a1, bq.z, bq.w);
            }
        }
#pragma unroll
        for (int a = 0; a < 2; a++) {
            int row = (2*mtg + a)*16 + g;
#pragma unroll
            for (int c = 0; c < 8; c++) {
                int col = (8*nq + c)*8 + 2*tg;
                float2 bb = *(const float2*)&b3[col];
                *(float2*)&bufF[ row     *260 + col] =
                    make_float2(acc[a][c][0] + bb.x, acc[a][c][1] + bb.y);
                *(float2*)&bufF[(row + 8)*260 + col] =
                    make_float2(acc[a][c][2] + bb.x, acc[a][c][3] + bb.y);
            }
        }
    }
    __syncthreads();
    ln_rows_s<256, false, 16>(bufF, 260, ENC_R, g3, be3);
    __syncthreads();

    // mean over K=16 neighbor rows per query
    for (int idx = t; idx < ENC_G * 256; idx += 512) {
        int gq = idx >> 8, j = idx & 255;
        float s = 0.f;
#pragma unroll
        for (int r = 0; r < 16; r++) s += bufF[(gq*16 + r)*260 + j];
        g_agg[(size_t)(q0 + gq)*256 + j] = s * (1.0f/16.0f);
    }
}

// ---------------------------------------------------------------------------
// Kernel 3: aggregator via tf32 mma (proven R8 configuration, 89us).
// ---------------------------------------------------------------------------
#define AGG_RB 64
#define AGG_SMEM_FLOATS (16384 + 16640)

__global__ __launch_bounds__(512, 1) void agg_kernel(
    const float* __restrict__ ba1,
    const float* __restrict__ ga1, const float* __restrict__ bea1,
    const float* __restrict__ ba2,
    float* __restrict__ out)
{
    extern __shared__ float sm[];
    float* sATF = sm;            // 16384: A fragments (KT=32, MT=4)
    float* bufF = sm + 16384;    // 16640
    const int t = threadIdx.x;
    const int w = t >> 5;
    const int lane = t & 31;
    const int g = lane >> 2, tg = lane & 3;
    const size_t row0 = (size_t)blockIdx.x * AGG_RB;

    {
        float4* dst = (float4*)bufF;
        const float4* src = (const float4*)(g_agg + row0*256);
        for (int i = t; i < AGG_RB*256/4; i += 512) dst[i] = src[i];
    }
    __syncthreads();
    cvt_to_afrag<32, 4>(bufF, 256, sATF, t, 512);
    __syncthreads();

    const int mt2 = w & 1;
    const int ng  = w >> 1;

    {   // stage A: in @ Wa1 + ba1 -> bufF stride 260
        float acc[2][4][4];
#pragma unroll
        for (int a = 0; a < 2; a++)
#pragma unroll
            for (int c = 0; c < 4; c++)
#pragma unroll
                for (int k = 0; k < 4; k++) acc[a][c][k] = 0.f;
        const uint4* AT = (const uint4*)sATF;
        const uint4* BT = (const uint4*)g_Wa1f;
#pragma unroll 8
        for (int kt = 0; kt < 32; kt++) {
            uint4 a0 = AT[(kt*4 + mt2*2    )*32 + lane];
            uint4 a1 = AT[(kt*4 + mt2*2 + 1)*32 + lane];
            uint4 bq0 = BT[(kt*16 + 2*ng    )*32 + lane];
            uint4 bq1 = BT[(kt*16 + 2*ng + 1)*32 + lane];
            mma_tf32(acc[0][0], a0, bq0.x, bq0.y);
            mma_tf32(acc[0][1], a0, bq0.z, bq0.w);
            mma_tf32(acc[0][2], a0, bq1.x, bq1.y);
            mma_tf32(acc[0][3], a0, bq1.z, bq1.w);
            mma_tf32(acc[1][0], a1, bq0.x, bq0.y);
            mma_tf32(acc[1][1], a1, bq0.z, bq0.w);
            mma_tf32(acc[1][2], a1, bq1.x, bq1.y);
            mma_tf32(acc[1][3], a1, bq1.z, bq1.w);
        }
#pragma unroll
        for (int a = 0; a < 2; a++) {
            int row = (mt2*2 + a)*16 + g;
#pragma unroll
            for (int c = 0; c < 4; c++) {
                int col = (4*ng + c)*8 + 2*tg;
                float2 bb = *(const float2*)&ba1[col];
                *(float2*)&bufF[ row     *260 + col] =
                    make_float2(acc[a][c][0] + bb.x, acc[a][c][1] + bb.y);
                *(float2*)&bufF[(row + 8)*260 + col] =
                    make_float2(acc[a][c][2] + bb.x, acc[a][c][3] + bb.y);
            }
        }
    }
    __syncthreads();
    ln_rows_s<256, true, 16>(bufF, 260, AGG_RB, ga1, bea1);
    __syncthreads();
    cvt_to_afrag<32, 4>(bufF, 260, sATF, t, 512);
    __syncthreads();

    {   // stage B: mid @ Wa2 + ba2 -> out
        float acc[2][4][4];
#pragma unroll
        for (int a = 0; a < 2; a++)
#pragma unroll
            for (int c = 0; c < 4; c++)
#pragma unroll
                for (int k = 0; k < 4; k++) acc[a][c][k] = 0.f;
        const uint4* AT = (const uint4*)sATF;
        const uint4* BT = (const uint4*)g_Wa2f;
#pragma unroll 8
        for (int kt = 0; kt < 32; kt++) {
            uint4 a0 = AT[(kt*4 + mt2*2    )*32 + lane];
            uint4 a1 = AT[(kt*4 + mt2*2 + 1)*32 + lane];
            uint4 bq0 = BT[(kt*16 + 2*ng    )*32 + lane];
            uint4 bq1 = BT[(kt*16 + 2*ng + 1)*32 + lane];
            mma_tf32(acc[0][0], a0, bq0.x, bq0.y);
            mma_tf32(acc[0][1], a0, bq0.z, bq0.w);
            mma_tf32(acc[0][2], a0, bq1.x, bq1.y);
            mma_tf32(acc[0][3], a0, bq1.z, bq1.w);
            mma_tf32(acc[1][0], a1, bq0.x, bq0.y);
            mma_tf32(acc[1][1], a1, bq0.z, bq0.w);
            mma_tf32(acc[1][2], a1, bq1.x, bq1.y);
            mma_tf32(acc[1][3], a1, bq1.z, bq1.w);
        }
#pragma unroll
        for (int a = 0; a < 2; a++) {
            size_t row = row0 + (mt2*2 + a)*16 + g;
#pragma unroll
            for (int c = 0; c < 4; c++) {
                int col = (4*ng + c)*8 + 2*tg;
                float2 bb = *(const float2*)&ba2[col];
                *(float2*)&out[ row     *256 + col] =
                    make_float2(acc[a][c][0] + bb.x, acc[a][c][1] + bb.y);
                *(float2*)&out[(row + 8)*256 + col] =
                    make_float2(acc[a][c][2] + bb.x, acc[a][c][3] + bb.y);
            }
        }
    }
}

// ---------------------------------------------------------------------------
extern "C" void kernel_launch(void* const* d_in, const int* in_sizes, int n_in,
                              void* d_out, int out_size)
{
    const float* coords = (const float*)d_in[0];
    const float* W1  = (const float*)d_in[1];
    const float* b1  = (const float*)d_in[2];
    const float* g1  = (const float*)d_in[3];
    const float* be1 = (const float*)d_in[4];
    const float* W2  = (const float*)d_in[5];
    const float* b2  = (const float*)d_in[6];
    const float* g2  = (const float*)d_in[7];
    const float* be2 = (const float*)d_in[8];
    const float* W3  = (const float*)d_in[9];
    const float* b3  = (const float*)d_in[10];
    const float* g3  = (const float*)d_in[11];
    const float* be3 = (const float*)d_in[12];
    const float* Wa1 = (const float*)d_in[13];
    const float* ba1 = (const float*)d_in[14];
    const float* ga1 = (const float*)d_in[15];
    const float* bea1= (const float*)d_in[16];
    const float* Wa2 = (const float*)d_in[17];
    const float* ba2 = (const float*)d_in[18];
    float* out = (float*)d_out;

    cudaFuncSetAttribute(encoder_kernel,
                         cudaFuncAttributeMaxDynamicSharedMemorySize,
                         ENC_SMEM_FLOATS * (int)sizeof(float));
    cudaFuncSetAttribute(agg_kernel,
                         cudaFuncAttributeMaxDynamicSharedMemorySize,
                         AGG_SMEM_FLOATS * (int)sizeof(float));

    prep_kernel<<<(43008 + 255)/256, 256>>>(W2, W3, Wa1, Wa2);

    knn_kernel<<<B_ * (N_ / 128), 256>>>(coords);

    encoder_kernel<<<M_ / ENC_G, 512, ENC_SMEM_FLOATS * sizeof(float)>>>(
        coords, W1, b1, g1, be1, b2, g2, be2, b3, g3, be3);

    agg_kernel<<<M_ / AGG_RB, 512, AGG_SMEM_FLOATS * sizeof(float)>>>(
        ba1, ga1, bea1, ba2, out);
}

// round 12
// speedup vs baseline: 1.0249x; 1.0249x over previous
#include <cuda_runtime.h>
#include <math.h>
#include <stdint.h>

#define B_ 8
#define N_ 4096
#define K_ 16
#define D_ 256
#define M_ (B_*N_)          // 32768 query rows

__device__ int   g_idx[M_*K_];        // 2 MB
__device__ float g_agg[M_*D_];        // 33.5 MB

// tf32 fragment-major weights (filled by prep_kernel each launch)
__device__ float g_W2f [8*8*32*4];    // [kt8][ntp8][lane32][4]
__device__ float g_W3f [16*16*32*4];  // [kt16][ntp16][lane32][4]
__device__ float g_Wa1f[32*16*32*4];  // [kt32][ntp16][lane32][4]
__device__ float g_Wa2f[32*16*32*4];

// ---------------------------------------------------------------------------
__device__ __forceinline__ float tf32r(float x) {
    uint32_t u;
    asm("cvt.rna.tf32.f32 %0, %1;" : "=r"(u) : "f"(x));
    return __uint_as_float(u);
}
// D += A(m16k8,row) * B(k8n8,col); fp32 accum, tf32 inputs
__device__ __forceinline__ void mma_tf32(float* c, uint4 a, uint32_t b0, uint32_t b1) {
    asm volatile(
        "mma.sync.aligned.m16n8k8.row.col.f32.tf32.tf32.f32 "
        "{%0,%1,%2,%3}, {%4,%5,%6,%7}, {%8,%9}, {%0,%1,%2,%3};"
        : "+f"(c[0]), "+f"(c[1]), "+f"(c[2]), "+f"(c[3])
        : "r"(a.x), "r"(a.y), "r"(a.z), "r"(a.w), "r"(b0), "r"(b1));
}

// ---------------------------------------------------------------------------
// Kernel 0: convert weights to tf32 fragment-major layouts.
// ---------------------------------------------------------------------------
__global__ void prep_kernel(const float* __restrict__ W2, const float* __restrict__ W3,
                            const float* __restrict__ Wa1, const float* __restrict__ Wa2)
{
    int idx = blockIdx.x * 256 + threadIdx.x;   // 43008 total float4 entries
    if (idx >= 43008) return;
    const float* W; float* dst; int NT, NTP, r;
    if (idx < 2048)       { r = idx;         W = W2;  dst = g_W2f;  NT = 128; NTP = 8;  }
    else if (idx < 10240) { r = idx - 2048;  W = W3;  dst = g_W3f;  NT = 256; NTP = 16; }
    else if (idx < 26624) { r = idx - 10240; W = Wa1; dst = g_Wa1f; NT = 256; NTP = 16; }
    else                  { r = idx - 26624; W = Wa2; dst = g_Wa2f; NT = 256; NTP = 16; }
    int lane = r & 31, ntp = (r >> 5) % NTP, kt = (r >> 5) / NTP;
    int g = lane >> 2, tg = lane & 3;
    int nt0 = 2*ntp, nt1 = 2*ntp + 1;
    float4 v;
    v.x = tf32r(W[(kt*8 + tg    )*NT + nt0*8 + g]);
    v.y = tf32r(W[(kt*8 + tg + 4)*NT + nt0*8 + g]);
    v.z = tf32r(W[(kt*8 + tg    )*NT + nt1*8 + g]);
    v.w = tf32r(W[(kt*8 + tg + 4)*NT + nt1*8 + g]);
    ((float4*)dst)[(kt*NTP + ntp)*32 + lane] = v;
}

// ---------------------------------------------------------------------------
// Kernel 1: brute-force kNN — measured-optimal R2 configuration (FROZEN).
// ---------------------------------------------------------------------------
__global__ __launch_bounds__(256) void knn_kernel(const float* __restrict__ coords)
{
    __shared__ float4 tile[256];
    __shared__ float  sd[256 * K_];
    __shared__ int    si[256 * K_];

    const int t = threadIdx.x;
    const int b  = blockIdx.x >> 5;
    const int q0 = (blockIdx.x & 31) << 7;
    const int q  = q0 + (t & 127);
    const int half = t >> 7;
    const float* cb = coords + (size_t)b * N_ * 3;

    float qx = cb[q*3+0], qy = cb[q*3+1], qz = cb[q*3+2];
    float qsq = qx*qx + qy*qy + qz*qz;

    float best[K_]; int bidx[K_];
#pragma unroll
    for (int s = 0; s < K_; s++) { best[s] = 3.4e38f; bidx[s] = 0; }

    const int base = half * 2048;
    for (int c0 = 0; c0 < 2048; c0 += 128) {
        __syncthreads();
        {
            int m = (t < 128) ? (c0 + t) : (2048 + c0 + (t - 128));
            float x = cb[m*3+0], y = cb[m*3+1], z = cb[m*3+2];
            tile[t] = make_float4(x, y, z, x*x + y*y + z*z);
        }
        __syncthreads();
        const float4* tl = tile + half * 128;
#pragma unroll 4
        for (int mm = 0; mm < 128; mm++) {
            float4 c = tl[mm];
            float d2 = qsq + c.w - 2.0f*(qx*c.x + qy*c.y + qz*c.z);
            if (d2 < best[K_-1]) {
                float d = d2; int id = base + c0 + mm;
#pragma unroll
                for (int s = 0; s < K_; s++) {
                    if (d < best[s]) {
                        float td = best[s]; int ti = bidx[s];
                        best[s] = d; bidx[s] = id;
                        d = td; id = ti;
                    }
                }
            }
        }
    }

#pragma unroll
    for (int s = 0; s < K_; s++) { sd[t*K_ + s] = best[s]; si[t*K_ + s] = bidx[s]; }
    __syncthreads();

    if (t < 128) {
        const float* da = sd + t*K_;        const int* xa = si + t*K_;
        const float* db = sd + (t+128)*K_;  const int* xb = si + (t+128)*K_;
        int ia = 0, ib = 0;
        int* o = g_idx + (size_t)(b*N_ + q0 + t) * K_;
#pragma unroll
        for (int s = 0; s < K_; s++) {
            float va = (ia < K_) ? da[ia] : 3.4e38f;
            float vb = (ib < K_) ? db[ib] : 3.4e38f;
            bool takeA = (va < vb) || (va == vb && ((ia < K_ ? xa[ia] : 0x7fffffff) <
                                                    (ib < K_ ? xb[ib] : 0x7fffffff)));
            if (takeA) { o[s] = xa[ia]; ia++; }
            else       { o[s] = xb[ib]; ib++; }
        }
    }
}

// ---------------------------------------------------------------------------
// Warp-per-row LayerNorm with runtime row stride. NW warps per block.
// ---------------------------------------------------------------------------
template<int W, bool RELU, int NW>
__device__ __forceinline__ void ln_rows_s(float* buf, int stride, int rows,
                                          const float* __restrict__ g,
                                          const float* __restrict__ be)
{
    const int wid = threadIdx.x >> 5, lane = threadIdx.x & 31;
    constexpr int C = W / 32;
    for (int r = wid; r < rows; r += NW) {
        float* h = buf + r * stride;
        float v[C]; float s = 0.f;
#pragma unroll
        for (int i = 0; i < C; i++) { v[i] = h[lane + i*32]; s += v[i]; }
#pragma unroll
        for (int o = 16; o; o >>= 1) s += __shfl_xor_sync(0xffffffffu, s, o);
        float mean = s * (1.0f / W);
        float s2 = 0.f;
#pragma unroll
        for (int i = 0; i < C; i++) { float d = v[i] - mean; s2 += d*d; }
#pragma unroll
        for (int o = 16; o; o >>= 1) s2 += __shfl_xor_sync(0xffffffffu, s2, o);
        float rstd = rsqrtf(s2 * (1.0f / W) + 1e-5f);
#pragma unroll
        for (int i = 0; i < C; i++) {
            int c = lane + i*32;
            float o2 = (v[i] - mean) * rstd * g[c] + be[c];
            if (RELU) o2 = fmaxf(o2, 0.f);
            h[c] = o2;
        }
    }
}

// cvt fp32 smem matrix (16*MT rows x KT*8 cols, stride) -> A-fragment tf32.
template<int KT, int MT>
__device__ __forceinline__ void cvt_to_afrag(const float* src, int sstride,
                                             float* dstATF, int tid, int nthr)
{
    const int total = KT * MT * 32 * 4;
    for (int idx = tid; idx < total; idx += nthr) {
        int j    = idx & 3;
        int lane = (idx >> 2) & 31;
        int mt   = (idx >> 7) % MT;
        int kt   = (idx >> 7) / MT;
        int row  = mt*16 + (lane >> 2) + (j & 1)*8;
        int col  = kt*8 + (lane & 3) + ((j >> 1) & 1)*4;
        dstATF[idx] = tf32r(src[row*sstride + col]);
    }
}

// ---------------------------------------------------------------------------
// Kernel 2: fused geom features + encoder MLP (10->64->128->256) + mean over K
// One block = 8 queries = 128 rows, 512 threads (16 warps).
// Stage 3 fully fused: mma -> LN3 (register/shfl, two-pass variance) ->
// neighbor-mean -> g_agg, no stage-3 smem matrix at all.
// smem floats: bufF[17408] | sATF[16384] | stats[1024] = 139 KB
// ---------------------------------------------------------------------------
#define ENC_G 8
#define ENC_R 128
#define ENC_SMEM_FLOATS (17408 + 16384 + 1024)

__global__ __launch_bounds__(512, 1) void encoder_kernel(
    const float* __restrict__ coords,
    const float* __restrict__ W1, const float* __restrict__ b1,
    const float* __restrict__ g1, const float* __restrict__ be1,
    const float* __restrict__ b2,
    const float* __restrict__ g2, const float* __restrict__ be2,
    const float* __restrict__ b3,
    const float* __restrict__ g3, const float* __restrict__ be3)
{
    extern __shared__ float sm[];
    float* bufF  = sm;                    // 17408 (stride 64 then 136)
    float* sATF  = sm + 17408;            // 16384 (geom first, then A-fragments)
    float* sstat = sm + 17408 + 16384;    // 1024: [4 nq][128 rows] x 2 rounds
    const int t = threadIdx.x;
    const int w = t >> 5;
    const int lane = t & 31;
    const int g = lane >> 2, tg = lane & 3;
    const int q0 = blockIdx.x * ENC_G;

    {   // geometric features, 4 threads per row (ph 0 = dist/rel/rn, 1-3 = one atan2)
        int row = t >> 2;
        int ph  = t & 3;
        int q  = q0 + (row >> 4);
        int kk = row & 15;
        int b  = q >> 12;
        int n  = q & (N_ - 1);
        const float* cb = coords + (size_t)b * N_ * 3;
        float qx = cb[n*3+0], qy = cb[n*3+1], qz = cb[n*3+2];
        int nb = g_idx[(size_t)q * K_ + kk];
        float rx = cb[nb*3+0] - qx, ry = cb[nb*3+1] - qy, rz = cb[nb*3+2] - qz;
        float dist = sqrtf(rx*rx + ry*ry + rz*rz);
        float inv  = 1.0f / (dist + 1e-6f);
        float nx = rx*inv, ny = ry*inv, nz = rz*inv;
        float* gm = sATF + row * 10;
        if (ph == 0) {
            gm[0] = dist; gm[1] = rx; gm[2] = ry; gm[3] = rz;
            gm[7] = nx; gm[8] = ny; gm[9] = nz;
        } else if (ph == 1) {
            gm[4] = atan2f(ny, nx);
        } else if (ph == 2) {
            gm[5] = atan2f(nz, nx);
        } else {
            gm[6] = atan2f(nz, ny);
        }
    }
    __syncthreads();

    // ---- stage 1 (fp32): geom[128][10] @ W1[10][64] -> bufF stride 64 ----
    {
        int j = t & 63, r0 = (t >> 6) * 16;
        float acc[16];
        float bj = b1[j];
#pragma unroll
        for (int r = 0; r < 16; r++) acc[r] = bj;
#pragma unroll
        for (int k = 0; k < 10; k++) {
            float wv = W1[k*64 + j];
#pragma unroll
            for (int r = 0; r < 16; r++)
                acc[r] = fmaf(wv, sATF[(r0 + r)*10 + k], acc[r]);
        }
#pragma unroll
        for (int r = 0; r < 16; r++) bufF[(r0 + r)*64 + j] = acc[r];
    }
    __syncthreads();
    ln_rows_s<64, true, 16>(bufF, 64, ENC_R, g1, be1);
    __syncthreads();

    // cvt h1 -> A-fragments (K=64 -> KT=8, MT=8)
    cvt_to_afrag<8, 8>(bufF, 64, sATF, t, 512);
    __syncthreads();

    // ---- stage 2 (mma): h1[128x64] @ W2[64x128] -> bufF stride 136 ----
    {
        const int mtg = w & 3;           // mtiles {2mtg, 2mtg+1}
        const int npg = w >> 2;          // ntps {2npg, 2npg+1} -> ntiles 4
        float acc[2][4][4];
#pragma unroll
        for (int a = 0; a < 2; a++)
#pragma unroll
            for (int c = 0; c < 4; c++)
#pragma unroll
                for (int k = 0; k < 4; k++) acc[a][c][k] = 0.f;
        const uint4* AT = (const uint4*)sATF;
        const uint4* BT = (const uint4*)g_W2f;
#pragma unroll
        for (int kt = 0; kt < 8; kt++) {
            uint4 a0 = AT[(kt*8 + 2*mtg    )*32 + lane];
            uint4 a1 = AT[(kt*8 + 2*mtg + 1)*32 + lane];
            uint4 bq0 = BT[(kt*8 + 2*npg    )*32 + lane];
            uint4 bq1 = BT[(kt*8 + 2*npg + 1)*32 + lane];
            mma_tf32(acc[0][0], a0, bq0.x, bq0.y);
            mma_tf32(acc[0][1], a0, bq0.z, bq0.w);
            mma_tf32(acc[0][2], a0, bq1.x, bq1.y);
            mma_tf32(acc[0][3], a0, bq1.z, bq1.w);
            mma_tf32(acc[1][0], a1, bq0.x, bq0.y);
            mma_tf32(acc[1][1], a1, bq0.z, bq0.w);
            mma_tf32(acc[1][2], a1, bq1.x, bq1.y);
            mma_tf32(acc[1][3], a1, bq1.z, bq1.w);
        }
#pragma unroll
        for (int a = 0; a < 2; a++) {
            int row = (2*mtg + a)*16 + g;
#pragma unroll
            for (int c = 0; c < 4; c++) {
                int col = (4*npg + c)*8 + 2*tg;
                float2 bb = *(const float2*)&b2[col];
                *(float2*)&bufF[ row     *136 + col] =
                    make_float2(acc[a][c][0] + bb.x, acc[a][c][1] + bb.y);
                *(float2*)&bufF[(row + 8)*136 + col] =
                    make_float2(acc[a][c][2] + bb.x, acc[a][c][3] + bb.y);
            }
        }
    }
    __syncthreads();
    ln_rows_s<128, true, 16>(bufF, 136, ENC_R, g2, be2);
    __syncthreads();

    // cvt h2 -> A-fragments (K=128 -> KT=16, MT=8)
    cvt_to_afrag<16, 8>(bufF, 136, sATF, t, 512);
    __syncthreads();

    // ---- stage 3 fused: mma + bias + LN3 (two-pass) + neighbor-mean -> g_agg ----
    // warp (mtg, nq): queries {2mtg, 2mtg+1} (one m-tile each), cols [64nq, 64nq+64)
    {
        const int mtg = w & 3;
        const int nq  = w >> 2;
        const uint4* AT = (const uint4*)sATF;
        const uint4* BT = (const uint4*)g_W3f;
        float acc[2][8][4];
#pragma unroll
        for (int a = 0; a < 2; a++)
#pragma unroll
            for (int c = 0; c < 8; c++)
#pragma unroll
                for (int k = 0; k < 4; k++) acc[a][c][k] = 0.f;
#pragma unroll
        for (int kt = 0; kt < 16; kt++) {
            uint4 a0 = AT[(kt*8 + 2*mtg    )*32 + lane];
            uint4 a1 = AT[(kt*8 + 2*mtg + 1)*32 + lane];
#pragma unroll
            for (int j = 0; j < 4; j++) {
                uint4 bq = BT[(kt*16 + 4*nq + j)*32 + lane];
                mma_tf32(acc[0][2*j    ], a0, bq.x, bq.y);
                mma_tf32(acc[0][2*j + 1], a0, bq.z, bq.w);
                mma_tf32(acc[1][2*j    ], a1, bq.x, bq.y);
                mma_tf32(acc[1][2*j + 1], a1, bq.z, bq.w);
            }
        }
        // add bias b3
#pragma unroll
        for (int c = 0; c < 8; c++) {
            float2 bb = *(const float2*)&b3[(8*nq + c)*8 + 2*tg];
#pragma unroll
            for (int a = 0; a < 2; a++) {
                acc[a][c][0] += bb.x; acc[a][c][1] += bb.y;
                acc[a][c][2] += bb.x; acc[a][c][3] += bb.y;
            }
        }
        // --- round 1: row sums (this warp's 64-col partials) ---
        float ps[2][2];
#pragma unroll
        for (int a = 0; a < 2; a++)
#pragma unroll
            for (int h = 0; h < 2; h++) {
                float s = 0.f;
#pragma unroll
                for (int c = 0; c < 8; c++) s += acc[a][c][2*h] + acc[a][c][2*h+1];
                s += __shfl_xor_sync(0xffffffffu, s, 1);
                s += __shfl_xor_sync(0xffffffffu, s, 2);
                ps[a][h] = s;
            }
        if (tg == 0) {
#pragma unroll
            for (int a = 0; a < 2; a++) {
                int r = (2*mtg + a)*16 + g;
                sstat[nq*128 + r    ] = ps[a][0];
                sstat[nq*128 + r + 8] = ps[a][1];
            }
        }
        __syncthreads();
        float mean[2][2];
#pragma unroll
        for (int a = 0; a < 2; a++)
#pragma unroll
            for (int h = 0; h < 2; h++) {
                int r = (2*mtg + a)*16 + g + h*8;
                mean[a][h] = (sstat[r] + sstat[128 + r] + sstat[256 + r] + sstat[384 + r])
                             * (1.0f/256.0f);
            }
        // --- round 2: sum of squared deviations ---
#pragma unroll
        for (int a = 0; a < 2; a++)
#pragma unroll
            for (int h = 0; h < 2; h++) {
                float s = 0.f;
#pragma unroll
                for (int c = 0; c < 8; c++) {
                    float d0 = acc[a][c][2*h]   - mean[a][h];
                    float d1 = acc[a][c][2*h+1] - mean[a][h];
                    s = fmaf(d0, d0, s); s = fmaf(d1, d1, s);
                }
                s += __shfl_xor_sync(0xffffffffu, s, 1);
                s += __shfl_xor_sync(0xffffffffu, s, 2);
                ps[a][h] = s;
            }
        __syncthreads();   // round-1 reads done before overwrite
        if (tg == 0) {
#pragma unroll
            for (int a = 0; a < 2; a++) {
                int r = (2*mtg + a)*16 + g;
                sstat[nq*128 + r    ] = ps[a][0];
                sstat[nq*128 + r + 8] = ps[a][1];
            }
        }
        __syncthreads();
        float rstd[2][2];
#pragma unroll
        for (int a = 0; a < 2; a++)
#pragma unroll
            for (int h = 0; h < 2; h++) {
                int r = (2*mtg + a)*16 + g + h*8;
                float var = (sstat[r] + sstat[128 + r] + sstat[256 + r] + sstat[384 + r])
                            * (1.0f/256.0f);
                rstd[a][h] = rsqrtf(var + 1e-5f);
            }
        // --- normalize + gamma/beta + sum over the 16 rows of each query ---
        float outs[2][8][2];
#pragma unroll
        for (int c = 0; c < 8; c++) {
            int col = (8*nq + c)*8 + 2*tg;
            float2 gg = *(const float2*)&g3[col];
            float2 bb = *(const float2*)&be3[col];
#pragma unroll
            for (int a = 0; a < 2; a++) {
                float x0 = (acc[a][c][0] - mean[a][0]) * rstd[a][0] * gg.x + bb.x;
                float x1 = (acc[a][c][1] - mean[a][0]) * rstd[a][0] * gg.y + bb.y;
                float x2 = (acc[a][c][2] - mean[a][1]) * rstd[a][1] * gg.x + bb.x;
                float x3 = (acc[a][c][3] - mean[a][1]) * rstd[a][1] * gg.y + bb.y;
                outs[a][c][0] = x0 + x2;
                outs[a][c][1] = x1 + x3;
            }
        }
#pragma unroll
        for (int a = 0; a < 2; a++)
#pragma unroll
            for (int c = 0; c < 8; c++)
#pragma unroll
                for (int j = 0; j < 2; j++) {
                    float v = outs[a][c][j];
                    v += __shfl_xor_sync(0xffffffffu, v, 4);
                    v += __shfl_xor_sync(0xffffffffu, v, 8);
                    v += __shfl_xor_sync(0xffffffffu, v, 16);
                    outs[a][c][j] = v;
                }
        if (g < 2) {
            int a = g;
            size_t q = (size_t)q0 + 2*mtg + a;
#pragma unroll
            for (int c = 0; c < 8; c++) {
                int col = (8*nq + c)*8 + 2*tg;
                *(float2*)&g_agg[q*256 + col] =
                    make_float2(outs[a][c][0] * (1.0f/16.0f),
                                outs[a][c][1] * (1.0f/16.0f));
            }
        }
    }
}

// ---------------------------------------------------------------------------
// Kernel 3: aggregator via tf32 mma (proven R8 configuration, 89us).
// ---------------------------------------------------------------------------
#define AGG_RB 64
#define AGG_SMEM_FLOATS (16384 + 16640)

__global__ __launch_bounds__(512, 1) void agg_kernel(
    const float* __restrict__ ba1,
    const float* __restrict__ ga1, const float* __restrict__ bea1,
    const float* __restrict__ ba2,
    float* __restrict__ out)
{
    extern __shared__ float sm[];
    float* sATF = sm;            // 16384: A fragments (KT=32, MT=4)
    float* bufF = sm + 16384;    // 16640
    const int t = threadIdx.x;
    const int w = t >> 5;
    const int lane = t & 31;
    const int g = lane >> 2, tg = lane & 3;
    const size_t row0 = (size_t)blockIdx.x * AGG_RB;

    {
        float4* dst = (float4*)bufF;
        const float4* src = (const float4*)(g_agg + row0*256);
        for (int i = t; i < AGG_RB*256/4; i += 512) dst[i] = src[i];
    }
    __syncthreads();
    cvt_to_afrag<32, 4>(bufF, 256, sATF, t, 512);
    __syncthreads();

    const int mt2 = w & 1;
    const int ng  = w >> 1;

    {   // stage A: in @ Wa1 + ba1 -> bufF stride 260
        float acc[2][4][4];
#pragma unroll
        for (int a = 0; a < 2; a++)
#pragma unroll
            for (int c = 0; c < 4; c++)
#pragma unroll
                for (int k = 0; k < 4; k++) acc[a][c][k] = 0.f;
        const uint4* AT = (const uint4*)sATF;
        const uint4* BT = (const uint4*)g_Wa1f;
#pragma unroll 8
        for (int kt = 0; kt < 32; kt++) {
            uint4 a0 = AT[(kt*4 + mt2*2    )*32 + lane];
            uint4 a1 = AT[(kt*4 + mt2*2 + 1)*32 + lane];
            uint4 bq0 = BT[(kt*16 + 2*ng    )*32 + lane];
            uint4 bq1 = BT[(kt*16 + 2*ng + 1)*32 + lane];
            mma_tf32(acc[0][0], a0, bq0.x, bq0.y);
            mma_tf32(acc[0][1], a0, bq0.z, bq0.w);
            mma_tf32(acc[0][2], a0, bq1.x, bq1.y);
            mma_tf32(acc[0][3], a0, bq1.z, bq1.w);
            mma_tf32(acc[1][0], a1, bq0.x, bq0.y);
            mma_tf32(acc[1][1], a1, bq0.z, bq0.w);
            mma_tf32(acc[1][2], a1, bq1.x, bq1.y);
            mma_tf32(acc[1][3], a1, bq1.z, bq1.w);
        }
#pragma unroll
        for (int a = 0; a < 2; a++) {
            int row = (mt2*2 + a)*16 + g;
#pragma unroll
            for (int c = 0; c < 4; c++) {
                int col = (4*ng + c)*8 + 2*tg;
                float2 bb = *(const float2*)&ba1[col];
                *(float2*)&bufF[ row     *260 + col] =
                    make_float2(acc[a][c][0] + bb.x, acc[a][c][1] + bb.y);
                *(float2*)&bufF[(row + 8)*260 + col] =
                    make_float2(acc[a][c][2] + bb.x, acc[a][c][3] + bb.y);
            }
        }
    }
    __syncthreads();
    ln_rows_s<256, true, 16>(bufF, 260, AGG_RB, ga1, bea1);
    __syncthreads();
    cvt_to_afrag<32, 4>(bufF, 260, sATF, t, 512);
    __syncthreads();

    {   // stage B: mid @ Wa2 + ba2 -> out
        float acc[2][4][4];
#pragma unroll
        for (int a = 0; a < 2; a++)
#pragma unroll
            for (int c = 0; c < 4; c++)
#pragma unroll
                for (int k = 0; k < 4; k++) acc[a][c][k] = 0.f;
        const uint4* AT = (const uint4*)sATF;
        const uint4* BT = (const uint4*)g_Wa2f;
#pragma unroll 8
        for (int kt = 0; kt < 32; kt++) {
            uint4 a0 = AT[(kt*4 + mt2*2    )*32 + lane];
            uint4 a1 = AT[(kt*4 + mt2*2 + 1)*32 + lane];
            uint4 bq0 = BT[(kt*16 + 2*ng    )*32 + lane];
            uint4 bq1 = BT[(kt*16 + 2*ng + 1)*32 + lane];
            mma_tf32(acc[0][0], a0, bq0.x, bq0.y);
            mma_tf32(acc[0][1], a0, bq0.z, bq0.w);
            mma_tf32(acc[0][2], a0, bq1.x, bq1.y);
            mma_tf32(acc[0][3], a0, bq1.z, bq1.w);
            mma_tf32(acc[1][0], a1, bq0.x, bq0.y);
            mma_tf32(acc[1][1], a1, bq0.z, bq0.w);
            mma_tf32(acc[1][2], a1, bq1.x, bq1.y);
            mma_tf32(acc[1][3], a1, bq1.z, bq1.w);
        }
#pragma unroll
        for (int a = 0; a < 2; a++) {
            size_t row = row0 + (mt2*2 + a)*16 + g;
#pragma unroll
            for (int c = 0; c < 4; c++) {
                int col = (4*ng + c)*8 + 2*tg;
                float2 bb = *(const float2*)&ba2[col];
                *(float2*)&out[ row     *256 + col] =
                    make_float2(acc[a][c][0] + bb.x, acc[a][c][1] + bb.y);
                *(float2*)&out[(row + 8)*256 + col] =
                    make_float2(acc[a][c][2] + bb.x, acc[a][c][3] + bb.y);
            }
        }
    }
}

// ---------------------------------------------------------------------------
extern "C" void kernel_launch(void* const* d_in, const int* in_sizes, int n_in,
                              void* d_out, int out_size)
{
    const float* coords = (const float*)d_in[0];
    const float* W1  = (const float*)d_in[1];
    const float* b1  = (const float*)d_in[2];
    const float* g1  = (const float*)d_in[3];
    const float* be1 = (const float*)d_in[4];
    const float* W2  = (const float*)d_in[5];
    const float* b2  = (const float*)d_in[6];
    const float* g2  = (const float*)d_in[7];
    const float* be2 = (const float*)d_in[8];
    const float* W3  = (const float*)d_in[9];
    const float* b3  = (const float*)d_in[10];
    const float* g3  = (const float*)d_in[11];
    const float* be3 = (const float*)d_in[12];
    const float* Wa1 = (const float*)d_in[13];
    const float* ba1 = (const float*)d_in[14];
    const float* ga1 = (const float*)d_in[15];
    const float* bea1= (const float*)d_in[16];
    const float* Wa2 = (const float*)d_in[17];
    const float* ba2 = (const float*)d_in[18];
    float* out = (float*)d_out;

    cudaFuncSetAttribute(encoder_kernel,
                         cudaFuncAttributeMaxDynamicSharedMemorySize,
                         ENC_SMEM_FLOATS * (int)sizeof(float));
    cudaFuncSetAttribute(agg_kernel,
                         cudaFuncAttributeMaxDynamicSharedMemorySize,
                         AGG_SMEM_FLOATS * (int)sizeof(float));

    prep_kernel<<<(43008 + 255)/256, 256>>>(W2, W3, Wa1, Wa2);

    knn_kernel<<<B_ * (N_ / 128), 256>>>(coords);

    encoder_kernel<<<M_ / ENC_G, 512, ENC_SMEM_FLOATS * sizeof(float)>>>(
        coords, W1, b1, g1, be1, b2, g2, be2, b3, g3, be3);

    agg_kernel<<<M_ / AGG_RB, 512, AGG_SMEM_FLOATS * sizeof(float)>>>(
        ba1, ga1, bea1, ba2, out);
}

// round 13
// speedup vs baseline: 1.1479x; 1.1200x over previous
#include <cuda_runtime.h>
#include <math.h>
#include <stdint.h>

#define B_ 8
#define N_ 4096
#define K_ 16
#define D_ 256
#define M_ (B_*N_)          // 32768 query rows

__device__ int   g_idx[M_*K_];        // 2 MB
__device__ float g_agg[M_*D_];        // 33.5 MB

// tf32 fragment-major weights (filled by prep_kernel each launch)
__device__ float g_W2f [8*8*32*4];    // [kt8][ntp8][lane32][4]
__device__ float g_W3f [16*16*32*4];  // [kt16][ntp16][lane32][4]
__device__ float g_Wa1f[32*16*32*4];  // [kt32][ntp16][lane32][4]
__device__ float g_Wa2f[32*16*32*4];

// ---------------------------------------------------------------------------
__device__ __forceinline__ float tf32r(float x) {
    uint32_t u;
    asm("cvt.rna.tf32.f32 %0, %1;" : "=r"(u) : "f"(x));
    return __uint_as_float(u);
}
// D += A(m16k8,row) * B(k8n8,col); fp32 accum, tf32 inputs
__device__ __forceinline__ void mma_tf32(float* c, uint4 a, uint32_t b0, uint32_t b1) {
    asm volatile(
        "mma.sync.aligned.m16n8k8.row.col.f32.tf32.tf32.f32 "
        "{%0,%1,%2,%3}, {%4,%5,%6,%7}, {%8,%9}, {%0,%1,%2,%3};"
        : "+f"(c[0]), "+f"(c[1]), "+f"(c[2]), "+f"(c[3])
        : "r"(a.x), "r"(a.y), "r"(a.z), "r"(a.w), "r"(b0), "r"(b1));
}

// ---------------------------------------------------------------------------
// Kernel 0: convert weights to tf32 fragment-major layouts.
// ---------------------------------------------------------------------------
__global__ void prep_kernel(const float* __restrict__ W2, const float* __restrict__ W3,
                            const float* __restrict__ Wa1, const float* __restrict__ Wa2)
{
    int idx = blockIdx.x * 256 + threadIdx.x;   // 43008 total float4 entries
    if (idx >= 43008) return;
    const float* W; float* dst; int NT, NTP, r;
    if (idx < 2048)       { r = idx;         W = W2;  dst = g_W2f;  NT = 128; NTP = 8;  }
    else if (idx < 10240) { r = idx - 2048;  W = W3;  dst = g_W3f;  NT = 256; NTP = 16; }
    else if (idx < 26624) { r = idx - 10240; W = Wa1; dst = g_Wa1f; NT = 256; NTP = 16; }
    else                  { r = idx - 26624; W = Wa2; dst = g_Wa2f; NT = 256; NTP = 16; }
    int lane = r & 31, ntp = (r >> 5) % NTP, kt = (r >> 5) / NTP;
    int g = lane >> 2, tg = lane & 3;
    int nt0 = 2*ntp, nt1 = 2*ntp + 1;
    float4 v;
    v.x = tf32r(W[(kt*8 + tg    )*NT + nt0*8 + g]);
    v.y = tf32r(W[(kt*8 + tg + 4)*NT + nt0*8 + g]);
    v.z = tf32r(W[(kt*8 + tg    )*NT + nt1*8 + g]);
    v.w = tf32r(W[(kt*8 + tg + 4)*NT + nt1*8 + g]);
    ((float4*)dst)[(kt*NTP + ntp)*32 + lane] = v;
}

// ---------------------------------------------------------------------------
// Kernel 1: brute-force kNN — measured-optimal R2 configuration (FROZEN).
// ---------------------------------------------------------------------------
__global__ __launch_bounds__(256) void knn_kernel(const float* __restrict__ coords)
{
    __shared__ float4 tile[256];
    __shared__ float  sd[256 * K_];
    __shared__ int    si[256 * K_];

    const int t = threadIdx.x;
    const int b  = blockIdx.x >> 5;
    const int q0 = (blockIdx.x & 31) << 7;
    const int q  = q0 + (t & 127);
    const int half = t >> 7;
    const float* cb = coords + (size_t)b * N_ * 3;

    float qx = cb[q*3+0], qy = cb[q*3+1], qz = cb[q*3+2];
    float qsq = qx*qx + qy*qy + qz*qz;

    float best[K_]; int bidx[K_];
#pragma unroll
    for (int s = 0; s < K_; s++) { best[s] = 3.4e38f; bidx[s] = 0; }

    const int base = half * 2048;
    for (int c0 = 0; c0 < 2048; c0 += 128) {
        __syncthreads();
        {
            int m = (t < 128) ? (c0 + t) : (2048 + c0 + (t - 128));
            float x = cb[m*3+0], y = cb[m*3+1], z = cb[m*3+2];
            tile[t] = make_float4(x, y, z, x*x + y*y + z*z);
        }
        __syncthreads();
        const float4* tl = tile + half * 128;
#pragma unroll 4
        for (int mm = 0; mm < 128; mm++) {
            float4 c = tl[mm];
            float d2 = qsq + c.w - 2.0f*(qx*c.x + qy*c.y + qz*c.z);
            if (d2 < best[K_-1]) {
                float d = d2; int id = base + c0 + mm;
#pragma unroll
                for (int s = 0; s < K_; s++) {
                    if (d < best[s]) {
                        float td = best[s]; int ti = bidx[s];
                        best[s] = d; bidx[s] = id;
                        d = td; id = ti;
                    }
                }
            }
        }
    }

#pragma unroll
    for (int s = 0; s < K_; s++) { sd[t*K_ + s] = best[s]; si[t*K_ + s] = bidx[s]; }
    __syncthreads();

    if (t < 128) {
        const float* da = sd + t*K_;        const int* xa = si + t*K_;
        const float* db = sd + (t+128)*K_;  const int* xb = si + (t+128)*K_;
        int ia = 0, ib = 0;
        int* o = g_idx + (size_t)(b*N_ + q0 + t) * K_;
#pragma unroll
        for (int s = 0; s < K_; s++) {
            float va = (ia < K_) ? da[ia] : 3.4e38f;
            float vb = (ib < K_) ? db[ib] : 3.4e38f;
            bool takeA = (va < vb) || (va == vb && ((ia < K_ ? xa[ia] : 0x7fffffff) <
                                                    (ib < K_ ? xb[ib] : 0x7fffffff)));
            if (takeA) { o[s] = xa[ia]; ia++; }
            else       { o[s] = xb[ib]; ib++; }
        }
    }
}

// ---------------------------------------------------------------------------
// Warp-per-row LayerNorm with runtime row stride. NW warps per block.
// ---------------------------------------------------------------------------
template<int W, bool RELU, int NW>
__device__ __forceinline__ void ln_rows_s(float* buf, int stride, int rows,
                                          const float* __restrict__ g,
                                          const float* __restrict__ be)
{
    const int wid = threadIdx.x >> 5, lane = threadIdx.x & 31;
    constexpr int C = W / 32;
    for (int r = wid; r < rows; r += NW) {
        float* h = buf + r * stride;
        float v[C]; float s = 0.f;
#pragma unroll
        for (int i = 0; i < C; i++) { v[i] = h[lane + i*32]; s += v[i]; }
#pragma unroll
        for (int o = 16; o; o >>= 1) s += __shfl_xor_sync(0xffffffffu, s, o);
        float mean = s * (1.0f / W);
        float s2 = 0.f;
#pragma unroll
        for (int i = 0; i < C; i++) { float d = v[i] - mean; s2 += d*d; }
#pragma unroll
        for (int o = 16; o; o >>= 1) s2 += __shfl_xor_sync(0xffffffffu, s2, o);
        float rstd = rsqrtf(s2 * (1.0f / W) + 1e-5f);
#pragma unroll
        for (int i = 0; i < C; i++) {
            int c = lane + i*32;
            float o2 = (v[i] - mean) * rstd * g[c] + be[c];
            if (RELU) o2 = fmaxf(o2, 0.f);
            h[c] = o2;
        }
    }
}

// cvt fp32 smem matrix (16*MT rows x KT*8 cols, stride) -> A-fragment tf32.
template<int KT, int MT>
__device__ __forceinline__ void cvt_to_afrag(const float* src, int sstride,
                                             float* dstATF, int tid, int nthr)
{
    const int total = KT * MT * 32 * 4;
    for (int idx = tid; idx < total; idx += nthr) {
        int j    = idx & 3;
        int lane = (idx >> 2) & 31;
        int mt   = (idx >> 7) % MT;
        int kt   = (idx >> 7) / MT;
        int row  = mt*16 + (lane >> 2) + (j & 1)*8;
        int col  = kt*8 + (lane & 3) + ((j >> 1) & 1)*4;
        dstATF[idx] = tf32r(src[row*sstride + col]);
    }
}

// ---------------------------------------------------------------------------
// Kernel 2: fused geom features + encoder MLP (10->64->128->256) + mean over K
// One block = 4 queries = 64 rows, 256 threads (8 warps), 2 blocks/SM.
// Stage 2: mma -> LN2 (cross-warp) -> ReLU -> scatter to tf32 A-frags (no
//   stride-136 buffer, no LN2 sweep, no cvt2 pass).
// Stage 3: mma -> LN3 -> neighbor-mean -> g_agg (as R12, 8-warp indices).
// smem floats: bufF[4096] | sATF[8192] | sstat[256] = 50176 B  (x2/SM)
// ---------------------------------------------------------------------------
#define ENC_G 4
#define ENC_R 64
#define ENC_SMEM_FLOATS (4096 + 8192 + 256)

__global__ __launch_bounds__(256, 2) void encoder_kernel(
    const float* __restrict__ coords,
    const float* __restrict__ W1, const float* __restrict__ b1,
    const float* __restrict__ g1, const float* __restrict__ be1,
    const float* __restrict__ b2,
    const float* __restrict__ g2, const float* __restrict__ be2,
    const float* __restrict__ b3,
    const float* __restrict__ g3, const float* __restrict__ be3)
{
    extern __shared__ float sm[];
    float* bufF  = sm;                 // 4096 (h1, stride 64)
    float* sATF  = sm + 4096;          // 8192 (geom, then h1-frags, then h2-frags)
    float* sstat = sm + 4096 + 8192;   // 256
    const int t = threadIdx.x;
    const int w = t >> 5;
    const int lane = t & 31;
    const int g = lane >> 2, tg = lane & 3;
    const int q0 = blockIdx.x * ENC_G;

    {   // geometric features, 4 threads per row (ph 0 = dist/rel/rn, 1-3 = one atan2)
        int row = t >> 2;              // 0..63
        int ph  = t & 3;
        int q  = q0 + (row >> 4);
        int kk = row & 15;
        int b  = q >> 12;
        int n  = q & (N_ - 1);
        const float* cb = coords + (size_t)b * N_ * 3;
        float qx = cb[n*3+0], qy = cb[n*3+1], qz = cb[n*3+2];
        int nb = g_idx[(size_t)q * K_ + kk];
        float rx = cb[nb*3+0] - qx, ry = cb[nb*3+1] - qy, rz = cb[nb*3+2] - qz;
        float dist = sqrtf(rx*rx + ry*ry + rz*rz);
        float inv  = 1.0f / (dist + 1e-6f);
        float nx = rx*inv, ny = ry*inv, nz = rz*inv;
        float* gm = sATF + row * 10;
        if (ph == 0) {
            gm[0] = dist; gm[1] = rx; gm[2] = ry; gm[3] = rz;
            gm[7] = nx; gm[8] = ny; gm[9] = nz;
        } else if (ph == 1) {
            gm[4] = atan2f(ny, nx);
        } else if (ph == 2) {
            gm[5] = atan2f(nz, nx);
        } else {
            gm[6] = atan2f(nz, ny);
        }
    }
    __syncthreads();

    // ---- stage 1 (fp32): geom[64][10] @ W1[10][64] -> bufF stride 64 ----
    {
        int j = t & 63, r0 = (t >> 6) * 16;   // 4 chunks x 16 rows
        float acc[16];
        float bj = b1[j];
#pragma unroll
        for (int r = 0; r < 16; r++) acc[r] = bj;
#pragma unroll
        for (int k = 0; k < 10; k++) {
            float wv = W1[k*64 + j];
#pragma unroll
            for (int r = 0; r < 16; r++)
                acc[r] = fmaf(wv, sATF[(r0 + r)*10 + k], acc[r]);
        }
#pragma unroll
        for (int r = 0; r < 16; r++) bufF[(r0 + r)*64 + j] = acc[r];
    }
    __syncthreads();
    ln_rows_s<64, true, 8>(bufF, 64, ENC_R, g1, be1);
    __syncthreads();

    // cvt h1 -> A-fragments (K=64 -> KT=8, MT=4), overwrites geom region
    cvt_to_afrag<8, 4>(bufF, 64, sATF, t, 256);
    __syncthreads();

    // ---- stage 2 fused: mma + bias + LN2 + ReLU -> h2 A-frags in sATF ----
    // warp (mtg = w&1, npg = w>>1): rows [32mtg,32mtg+32), cols [32npg,32npg+32)
    {
        const int mtg = w & 1;
        const int npg = w >> 1;
        float acc[2][4][4];
#pragma unroll
        for (int a = 0; a < 2; a++)
#pragma unroll
            for (int c = 0; c < 4; c++)
#pragma unroll
                for (int k = 0; k < 4; k++) acc[a][c][k] = 0.f;
        const uint4* AT = (const uint4*)sATF;
        const uint4* BT = (const uint4*)g_W2f;
#pragma unroll
        for (int kt = 0; kt < 8; kt++) {
            uint4 a0 = AT[(kt*4 + 2*mtg    )*32 + lane];
            uint4 a1 = AT[(kt*4 + 2*mtg + 1)*32 + lane];
            uint4 bq0 = BT[(kt*8 + 2*npg    )*32 + lane];
            uint4 bq1 = BT[(kt*8 + 2*npg + 1)*32 + lane];
            mma_tf32(acc[0][0], a0, bq0.x, bq0.y);
            mma_tf32(acc[0][1], a0, bq0.z, bq0.w);
            mma_tf32(acc[0][2], a0, bq1.x, bq1.y);
            mma_tf32(acc[0][3], a0, bq1.z, bq1.w);
            mma_tf32(acc[1][0], a1, bq0.x, bq0.y);
            mma_tf32(acc[1][1], a1, bq0.z, bq0.w);
            mma_tf32(acc[1][2], a1, bq1.x, bq1.y);
            mma_tf32(acc[1][3], a1, bq1.z, bq1.w);
        }
        // bias b2
#pragma unroll
        for (int c = 0; c < 4; c++) {
            float2 bb = *(const float2*)&b2[(4*npg + c)*8 + 2*tg];
#pragma unroll
            for (int a = 0; a < 2; a++) {
                acc[a][c][0] += bb.x; acc[a][c][1] += bb.y;
                acc[a][c][2] += bb.x; acc[a][c][3] += bb.y;
            }
        }
        // round 1: row sums of this warp's 32 cols
        float ps[2][2];
#pragma unroll
        for (int a = 0; a < 2; a++)
#pragma unroll
            for (int h = 0; h < 2; h++) {
                float s = 0.f;
#pragma unroll
                for (int c = 0; c < 4; c++) s += acc[a][c][2*h] + acc[a][c][2*h+1];
                s += __shfl_xor_sync(0xffffffffu, s, 1);
                s += __shfl_xor_sync(0xffffffffu, s, 2);
                ps[a][h] = s;
            }
        if (tg == 0) {
#pragma unroll
            for (int a = 0; a < 2; a++) {
                int r = (2*mtg + a)*16 + g;
                sstat[npg*64 + r    ] = ps[a][0];
                sstat[npg*64 + r + 8] = ps[a][1];
            }
        }
        __syncthreads();
        float mean[2][2];
#pragma unroll
        for (int a = 0; a < 2; a++)
#pragma unroll
            for (int h = 0; h < 2; h++) {
                int r = (2*mtg + a)*16 + g + h*8;
                mean[a][h] = (sstat[r] + sstat[64 + r] + sstat[128 + r] + sstat[192 + r])
                             * (1.0f/128.0f);
            }
        // round 2: squared deviations
#pragma unroll
        for (int a = 0; a < 2; a++)
#pragma unroll
            for (int h = 0; h < 2; h++) {
                float s = 0.f;
#pragma unroll
                for (int c = 0; c < 4; c++) {
                    float d0 = acc[a][c][2*h]   - mean[a][h];
                    float d1 = acc[a][c][2*h+1] - mean[a][h];
                    s = fmaf(d0, d0, s); s = fmaf(d1, d1, s);
                }
                s += __shfl_xor_sync(0xffffffffu, s, 1);
                s += __shfl_xor_sync(0xffffffffu, s, 2);
                ps[a][h] = s;
            }
        __syncthreads();
        if (tg == 0) {
#pragma unroll
            for (int a = 0; a < 2; a++) {
                int r = (2*mtg + a)*16 + g;
                sstat[npg*64 + r    ] = ps[a][0];
                sstat[npg*64 + r + 8] = ps[a][1];
            }
        }
        __syncthreads();
        float rstd[2][2];
#pragma unroll
        for (int a = 0; a < 2; a++)
#pragma unroll
            for (int h = 0; h < 2; h++) {
                int r = (2*mtg + a)*16 + g + h*8;
                float var = (sstat[r] + sstat[64 + r] + sstat[128 + r] + sstat[192 + r])
                            * (1.0f/128.0f);
                rstd[a][h] = rsqrtf(var + 1e-5f);
            }
        // normalize + ReLU + scatter directly into h2 A-frag layout (KT=16, MT=4)
        // (all warps finished reading h1 frags before the first __syncthreads)
#pragma unroll
        for (int a = 0; a < 2; a++) {
            int mt = 2*mtg + a;
#pragma unroll
            for (int c = 0; c < 4; c++) {
                int kt = 4*npg + c;
                float2 gg = *(const float2*)&g2[kt*8 + 2*tg];
                float2 bb = *(const float2*)&be2[kt*8 + 2*tg];
#pragma unroll
                for (int h = 0; h < 2; h++)
#pragma unroll
                    for (int e = 0; e < 2; e++) {
                        float v = (acc[a][c][2*h + e] - mean[a][h]) * rstd[a][h]
                                  * (e ? gg.y : gg.x) + (e ? bb.y : bb.x);
                        v = fmaxf(v, 0.f);
                        int ic   = 2*tg + e;
                        int lanep= g*4 + (ic & 3);
                        int j    = h + 2*(ic >> 2);
                        sATF[((kt*4 + mt)*32 + lanep)*4 + j] = tf32r(v);
                    }
            }
        }
    }
    __syncthreads();

    // ---- stage 3 fused: mma + bias + LN3 (two-pass) + neighbor-mean -> g_agg ----
    // warp (mtg = w&1, nq = w>>1): queries {2mtg, 2mtg+1}, cols [64nq, 64nq+64)
    {
        const int mtg = w & 1;
        const int nq  = w >> 1;
        const uint4* AT = (const uint4*)sATF;
        const uint4* BT = (const uint4*)g_W3f;
        float acc[2][8][4];
#pragma unroll
        for (int a = 0; a < 2; a++)
#pragma unroll
            for (int c = 0; c < 8; c++)
#pragma unroll
                for (int k = 0; k < 4; k++) acc[a][c][k] = 0.f;
#pragma unroll
        for (int kt = 0; kt < 16; kt++) {
            uint4 a0 = AT[(kt*4 + 2*mtg    )*32 + lane];
            uint4 a1 = AT[(kt*4 + 2*mtg + 1)*32 + lane];
#pragma unroll
            for (int j = 0; j < 4; j++) {
                uint4 bq = BT[(kt*16 + 4*nq + j)*32 + lane];
                mma_tf32(acc[0][2*j    ], a0, bq.x, bq.y);
                mma_tf32(acc[0][2*j + 1], a0, bq.z, bq.w);
                mma_tf32(acc[1][2*j    ], a1, bq.x, bq.y);
                mma_tf32(acc[1][2*j + 1], a1, bq.z, bq.w);
            }
        }
        // bias b3
#pragma unroll
        for (int c = 0; c < 8; c++) {
            float2 bb = *(const float2*)&b3[(8*nq + c)*8 + 2*tg];
#pragma unroll
            for (int a = 0; a < 2; a++) {
                acc[a][c][0] += bb.x; acc[a][c][1] += bb.y;
                acc[a][c][2] += bb.x; acc[a][c][3] += bb.y;
            }
        }
        // round 1: row sums (this warp's 64-col partials)
        float ps[2][2];
#pragma unroll
        for (int a = 0; a < 2; a++)
#pragma unroll
            for (int h = 0; h < 2; h++) {
                float s = 0.f;
#pragma unroll
                for (int c = 0; c < 8; c++) s += acc[a][c][2*h] + acc[a][c][2*h+1];
                s += __shfl_xor_sync(0xffffffffu, s, 1);
                s += __shfl_xor_sync(0xffffffffu, s, 2);
                ps[a][h] = s;
            }
        if (tg == 0) {
#pragma unroll
            for (int a = 0; a < 2; a++) {
                int r = (2*mtg + a)*16 + g;
                sstat[nq*64 + r    ] = ps[a][0];
                sstat[nq*64 + r + 8] = ps[a][1];
            }
        }
        __syncthreads();
        float mean[2][2];
#pragma unroll
        for (int a = 0; a < 2; a++)
#pragma unroll
            for (int h = 0; h < 2; h++) {
                int r = (2*mtg + a)*16 + g + h*8;
                mean[a][h] = (sstat[r] + sstat[64 + r] + sstat[128 + r] + sstat[192 + r])
                             * (1.0f/256.0f);
            }
        // round 2: squared deviations
#pragma unroll
        for (int a = 0; a < 2; a++)
#pragma unroll
            for (int h = 0; h < 2; h++) {
                float s = 0.f;
#pragma unroll
                for (int c = 0; c < 8; c++) {
                    float d0 = acc[a][c][2*h]   - mean[a][h];
                    float d1 = acc[a][c][2*h+1] - mean[a][h];
                    s = fmaf(d0, d0, s); s = fmaf(d1, d1, s);
                }
                s += __shfl_xor_sync(0xffffffffu, s, 1);
                s += __shfl_xor_sync(0xffffffffu, s, 2);
                ps[a][h] = s;
            }
        __syncthreads();
        if (tg == 0) {
#pragma unroll
            for (int a = 0; a < 2; a++) {
                int r = (2*mtg + a)*16 + g;
                sstat[nq*64 + r    ] = ps[a][0];
                sstat[nq*64 + r + 8] = ps[a][1];
            }
        }
        __syncthreads();
        float rstd[2][2];
#pragma unroll
        for (int a = 0; a < 2; a++)
#pragma unroll
            for (int h = 0; h < 2; h++) {
                int r = (2*mtg + a)*16 + g + h*8;
                float var = (sstat[r] + sstat[64 + r] + sstat[128 + r] + sstat[192 + r])
                            * (1.0f/256.0f);
                rstd[a][h] = rsqrtf(var + 1e-5f);
            }
        // normalize + gamma/beta + sum over the 16 rows of each query
        float outs[2][8][2];
#pragma unroll
        for (int c = 0; c < 8; c++) {
            int col = (8*nq + c)*8 + 2*tg;
            float2 gg = *(const float2*)&g3[col];
            float2 bb = *(const float2*)&be3[col];
#pragma unroll
            for (int a = 0; a < 2; a++) {
                float x0 = (acc[a][c][0] - mean[a][0]) * rstd[a][0] * gg.x + bb.x;
                float x1 = (acc[a][c][1] - mean[a][0]) * rstd[a][0] * gg.y + bb.y;
                float x2 = (acc[a][c][2] - mean[a][1]) * rstd[a][1] * gg.x + bb.x;
                float x3 = (acc[a][c][3] - mean[a][1]) * rstd[a][1] * gg.y + bb.y;
                outs[a][c][0] = x0 + x2;
                outs[a][c][1] = x1 + x3;
            }
        }
#pragma unroll
        for (int a = 0; a < 2; a++)
#pragma unroll
            for (int c = 0; c < 8; c++)
#pragma unroll
                for (int j = 0; j < 2; j++) {
                    float v = outs[a][c][j];
                    v += __shfl_xor_sync(0xffffffffu, v, 4);
                    v += __shfl_xor_sync(0xffffffffu, v, 8);
                    v += __shfl_xor_sync(0xffffffffu, v, 16);
                    outs[a][c][j] = v;
                }
        if (g < 2) {
            int a = g;
            size_t q = (size_t)q0 + 2*mtg + a;
#pragma unroll
            for (int c = 0; c < 8; c++) {
                int col = (8*nq + c)*8 + 2*tg;
                *(float2*)&g_agg[q*256 + col] =
                    make_float2(outs[a][c][0] * (1.0f/16.0f),
                                outs[a][c][1] * (1.0f/16.0f));
            }
        }
    }
}

// ---------------------------------------------------------------------------
// Kernel 3: aggregator via tf32 mma (proven R8 configuration, 89us, FROZEN).
// ---------------------------------------------------------------------------
#define AGG_RB 64
#define AGG_SMEM_FLOATS (16384 + 16640)

__global__ __launch_bounds__(512, 1) void agg_kernel(
    const float* __restrict__ ba1,
    const float* __restrict__ ga1, const float* __restrict__ bea1,
    const float* __restrict__ ba2,
    float* __restrict__ out)
{
    extern __shared__ float sm[];
    float* sATF = sm;            // 16384: A fragments (KT=32, MT=4)
    float* bufF = sm + 16384;    // 16640
    const int t = threadIdx.x;
    const int w = t >> 5;
    const int lane = t & 31;
    const int g = lane >> 2, tg = lane & 3;
    const size_t row0 = (size_t)blockIdx.x * AGG_RB;

    {
        float4* dst = (float4*)bufF;
        const float4* src = (const float4*)(g_agg + row0*256);
        for (int i = t; i < AGG_RB*256/4; i += 512) dst[i] = src[i];
    }
    __syncthreads();
    cvt_to_afrag<32, 4>(bufF, 256, sATF, t, 512);
    __syncthreads();

    const int mt2 = w & 1;
    const int ng  = w >> 1;

    {   // stage A: in @ Wa1 + ba1 -> bufF stride 260
        float acc[2][4][4];
#pragma unroll
        for (int a = 0; a < 2; a++)
#pragma unroll
            for (int c = 0; c < 4; c++)
#pragma unroll
                for (int k = 0; k < 4; k++) acc[a][c][k] = 0.f;
        const uint4* AT = (const uint4*)sATF;
        const uint4* BT = (const uint4*)g_Wa1f;
#pragma unroll 8
        for (int kt = 0; kt < 32; kt++) {
            uint4 a0 = AT[(kt*4 + mt2*2    )*32 + lane];
            uint4 a1 = AT[(kt*4 + mt2*2 + 1)*32 + lane];
            uint4 bq0 = BT[(kt*16 + 2*ng    )*32 + lane];
            uint4 bq1 = BT[(kt*16 + 2*ng + 1)*32 + lane];
            mma_tf32(acc[0][0], a0, bq0.x, bq0.y);
            mma_tf32(acc[0][1], a0, bq0.z, bq0.w);
            mma_tf32(acc[0][2], a0, bq1.x, bq1.y);
            mma_tf32(acc[0][3], a0, bq1.z, bq1.w);
            mma_tf32(acc[1][0], a1, bq0.x, bq0.y);
            mma_tf32(acc[1][1], a1, bq0.z, bq0.w);
            mma_tf32(acc[1][2], a1, bq1.x, bq1.y);
            mma_tf32(acc[1][3], a1, bq1.z, bq1.w);
        }
#pragma unroll
        for (int a = 0; a < 2; a++) {
            int row = (mt2*2 + a)*16 + g;
#pragma unroll
            for (int c = 0; c < 4; c++) {
                int col = (4*ng + c)*8 + 2*tg;
                float2 bb = *(const float2*)&ba1[col];
                *(float2*)&bufF[ row     *260 + col] =
                    make_float2(acc[a][c][0] + bb.x, acc[a][c][1] + bb.y);
                *(float2*)&bufF[(row + 8)*260 + col] =
                    make_float2(acc[a][c][2] + bb.x, acc[a][c][3] + bb.y);
            }
        }
    }
    __syncthreads();
    ln_rows_s<256, true, 16>(bufF, 260, AGG_RB, ga1, bea1);
    __syncthreads();
    cvt_to_afrag<32, 4>(bufF, 260, sATF, t, 512);
    __syncthreads();

    {   // stage B: mid @ Wa2 + ba2 -> out
        float acc[2][4][4];
#pragma unroll
        for (int a = 0; a < 2; a++)
#pragma unroll
            for (int c = 0; c < 4; c++)
#pragma unroll
                for (int k = 0; k < 4; k++) acc[a][c][k] = 0.f;
        const uint4* AT = (const uint4*)sATF;
        const uint4* BT = (const uint4*)g_Wa2f;
#pragma unroll 8
        for (int kt = 0; kt < 32; kt++) {
            uint4 a0 = AT[(kt*4 + mt2*2    )*32 + lane];
            uint4 a1 = AT[(kt*4 + mt2*2 + 1)*32 + lane];
            uint4 bq0 = BT[(kt*16 + 2*ng    )*32 + lane];
            uint4 bq1 = BT[(kt*16 + 2*ng + 1)*32 + lane];
            mma_tf32(acc[0][0], a0, bq0.x, bq0.y);
            mma_tf32(acc[0][1], a0, bq0.z, bq0.w);
            mma_tf32(acc[0][2], a0, bq1.x, bq1.y);
            mma_tf32(acc[0][3], a0, bq1.z, bq1.w);
            mma_tf32(acc[1][0], a1, bq0.x, bq0.y);
            mma_tf32(acc[1][1], a1, bq0.z, bq0.w);
            mma_tf32(acc[1][2], a1, bq1.x, bq1.y);
            mma_tf32(acc[1][3], a1, bq1.z, bq1.w);
        }
#pragma unroll
        for (int a = 0; a < 2; a++) {
            size_t row = row0 + (mt2*2 + a)*16 + g;
#pragma unroll
            for (int c = 0; c < 4; c++) {
                int col = (4*ng + c)*8 + 2*tg;
                float2 bb = *(const float2*)&ba2[col];
                *(float2*)&out[ row     *256 + col] =
                    make_float2(acc[a][c][0] + bb.x, acc[a][c][1] + bb.y);
                *(float2*)&out[(row + 8)*256 + col] =
                    make_float2(acc[a][c][2] + bb.x, acc[a][c][3] + bb.y);
            }
        }
    }
}

// ---------------------------------------------------------------------------
extern "C" void kernel_launch(void* const* d_in, const int* in_sizes, int n_in,
                              void* d_out, int out_size)
{
    const float* coords = (const float*)d_in[0];
    const float* W1  = (const float*)d_in[1];
    const float* b1  = (const float*)d_in[2];
    const float* g1  = (const float*)d_in[3];
    const float* be1 = (const float*)d_in[4];
    const float* W2  = (const float*)d_in[5];
    const float* b2  = (const float*)d_in[6];
    const float* g2  = (const float*)d_in[7];
    const float* be2 = (const float*)d_in[8];
    const float* W3  = (const float*)d_in[9];
    const float* b3  = (const float*)d_in[10];
    const float* g3  = (const float*)d_in[11];
    const float* be3 = (const float*)d_in[12];
    const float* Wa1 = (const float*)d_in[13];
    const float* ba1 = (const float*)d_in[14];
    const float* ga1 = (const float*)d_in[15];
    const float* bea1= (const float*)d_in[16];
    const float* Wa2 = (const float*)d_in[17];
    const float* ba2 = (const float*)d_in[18];
    float* out = (float*)d_out;

    cudaFuncSetAttribute(encoder_kernel,
                         cudaFuncAttributeMaxDynamicSharedMemorySize,
                         ENC_SMEM_FLOATS * (int)sizeof(float));
    cudaFuncSetAttribute(agg_kernel,
                         cudaFuncAttributeMaxDynamicSharedMemorySize,
                         AGG_SMEM_FLOATS * (int)sizeof(float));

    prep_kernel<<<(43008 + 255)/256, 256>>>(W2, W3, Wa1, Wa2);

    knn_kernel<<<B_ * (N_ / 128), 256>>>(coords);

    encoder_kernel<<<M_ / ENC_G, 256, ENC_SMEM_FLOATS * sizeof(float)>>>(
        coords, W1, b1, g1, be1, b2, g2, be2, b3, g3, be3);

    agg_kernel<<<M_ / AGG_RB, 512, AGG_SMEM_FLOATS * sizeof(float)>>>(
        ba1, ga1, bea1, ba2, out);
}